// round 7
// baseline (speedup 1.0000x reference)
#include <cuda_runtime.h>
#include <math_constants.h>

// ---------------------------------------------------------------------------
// Problem constants
// ---------------------------------------------------------------------------
#define BATCH 2
#define M_PTS 4096
#define NQ (BATCH * M_PTS)          // 8192 queries
#define N1 16384
#define N2 8192
#define N3 4096
#define PT1 0                        // set-major point offsets (batch folded in)
#define PT2 32768
#define PT3 49152
#define NPT 57344                    // total HR points (all sets, both batches)

// spatial hash grid: 1m cells covering x[0,72) y[-40,40) z[-3,1)
#define GX 72
#define GY 80
#define GZ 4
#define NCELL (GX * GY * GZ)         // 23040
#define SEGSTRIDE (NCELL + 1)        // +1 sentinel for range-end lookups
#define NSEG 6                       // 3 sets x 2 batches
#define TOTC (NSEG * SEGSTRIDE)

#define FULLM 0xffffffffu

// smem weight layout offsets: per set rows[(3+C)*32] then bias[32]
#define WOFF1 0            // 19*32 = 608 rows, bias at 608
#define WOFF2 640          // 35*32 = 1120 rows, bias at 1760
#define WOFF3 1792         // 67*32 = 2144 rows, bias at 3936
#define WTOT  3968

// ---------------------------------------------------------------------------
// Static device scratch (no allocations allowed).
// g_cnt: prep increments, scatter decrements back to zero -> self-restoring
// across graph replays (no memset needed).
// ---------------------------------------------------------------------------
__device__ float4 g_lr[NQ];
__device__ float4 g_hr[NPT];
__device__ int    g_cellid[NPT];
__device__ int    g_cnt[TOTC];
__device__ int    g_startArr[TOTC];   // per-segment exclusive prefix + sentinel
__device__ float4 g_sorted4[NPT];     // (x,y,z, idx-as-float), cell-grouped

// ---------------------------------------------------------------------------
// K1: xyz (exact ref rounding) + cell id + cell histogram
// ---------------------------------------------------------------------------
__global__ void prep_kernel(const int* __restrict__ lr_idx,
                            const int* __restrict__ h1_idx,
                            const int* __restrict__ h2_idx,
                            const int* __restrict__ h3_idx) {
    int tid = blockIdx.x * blockDim.x + threadIdx.x;  // 65536 = NQ + NPT
    const int* idx; int s, local, nsh = 0, ptOff = 0;
    float vx, vy, vz;
    if (tid < NQ) {
        s = -1; local = tid; idx = lr_idx; vx = 0.4f; vy = 0.4f; vz = 1.0f;
    } else {
        int p = tid - NQ;
        if (p < PT2)      { s = 0; local = p;       nsh = 14; ptOff = PT1; idx = h1_idx; vx = 0.05f; vy = 0.05f; vz = 0.1f; }
        else if (p < PT3) { s = 1; local = p - PT2; nsh = 13; ptOff = PT2; idx = h2_idx; vx = 0.1f;  vy = 0.1f;  vz = 0.2f; }
        else              { s = 2; local = p - PT3; nsh = 12; ptOff = PT3; idx = h3_idx; vx = 0.2f;  vy = 0.2f;  vz = 0.4f; }
    }
    int zi = idx[3 * local], yi = idx[3 * local + 1], xi = idx[3 * local + 2];
    // exact replication of ((i*vs)+off)+0.5*vs, no fma contraction
    float fx = __fadd_rn(__fadd_rn(__fmul_rn((float)xi, vx), 0.0f),   __fmul_rn(0.5f, vx));
    float fy = __fadd_rn(__fadd_rn(__fmul_rn((float)yi, vy), -40.0f), __fmul_rn(0.5f, vy));
    float fz = __fadd_rn(__fadd_rn(__fmul_rn((float)zi, vz), -3.0f),  __fmul_rn(0.5f, vz));
    float4 p4 = make_float4(fx, fy, fz, 0.0f);
    if (s < 0) {
        g_lr[local] = p4;
    } else {
        int gp = ptOff + local;
        g_hr[gp] = p4;
        int b = local >> nsh;
        int cx = (int)floorf(fx);
        int cy = (int)floorf(fy + 40.0f);
        int cz = (int)floorf(fz + 3.0f);
        int gc = (s * 2 + b) * SEGSTRIDE + (cz * GY + cy) * GX + cx;
        g_cellid[gp] = gc;
        atomicAdd(&g_cnt[gc], 1);
    }
}

// ---------------------------------------------------------------------------
// K2: fused per-segment scan + scatter. Block = segment (6 blocks x 1024).
// Each segment's points occupy a contiguous global range, so after the
// in-block scan completes (__syncthreads) the same block scatters them.
// Scatter decrements g_cnt back to zero (self-restoring for graph replay).
// ---------------------------------------------------------------------------
#define CHUNK 23   // ceil(23040 / 1024)
__constant__ int c_segPt0[NSEG] = {0, 16384, 32768, 40960, 49152, 53248};
__constant__ int c_segPt1[NSEG] = {16384, 32768, 40960, 49152, 53248, 57344};
__constant__ int c_segNsh[NSEG] = {14, 14, 13, 13, 12, 12};
__constant__ int c_segOff[NSEG] = {PT1, PT1, PT2, PT2, PT3, PT3};

__global__ __launch_bounds__(1024) void scan_scatter_kernel() {
    __shared__ int warpTot[32];
    const int seg = blockIdx.x;
    const int base = seg * SEGSTRIDE;
    const int t = threadIdx.x, lane = t & 31, wid = t >> 5;

    // ---- scan ----
    int c0 = t * CHUNK;
    int sum = 0;
    #pragma unroll
    for (int k = 0; k < CHUNK; ++k) {
        int c = c0 + k;
        if (c < NCELL) sum += g_cnt[base + c];
    }
    int inc = sum;
    #pragma unroll
    for (int d = 1; d < 32; d <<= 1) {
        int u = __shfl_up_sync(FULLM, inc, d);
        if (lane >= d) inc += u;
    }
    if (lane == 31) warpTot[wid] = inc;
    __syncthreads();
    if (wid == 0) {
        int wv = warpTot[lane];
        #pragma unroll
        for (int d = 1; d < 32; d <<= 1) {
            int u = __shfl_up_sync(FULLM, wv, d);
            if (lane >= d) wv += u;
        }
        warpTot[lane] = wv;
    }
    __syncthreads();
    int ex = inc - sum + (wid > 0 ? warpTot[wid - 1] : 0);
    #pragma unroll
    for (int k = 0; k < CHUNK; ++k) {
        int c = c0 + k;
        if (c < NCELL) {
            int cc = g_cnt[base + c];
            g_startArr[base + c] = ex;
            ex += cc;
        }
    }
    if (t == 1023) g_startArr[base + NCELL] = ex;   // sentinel = segment total
    __syncthreads();

    // ---- scatter this segment's points ----
    const int p0 = c_segPt0[seg], p1 = c_segPt1[seg];
    const int nsh = c_segNsh[seg], ptOff = c_segOff[seg];
    for (int tidp = p0 + t; tidp < p1; tidp += 1024) {
        int local = tidp - ptOff;
        int gc = g_cellid[tidp];
        int pos = g_startArr[gc] + atomicAdd(&g_cnt[gc], -1) - 1;
        int b = local >> nsh;
        int i = local - (b << nsh);              // in-batch index
        float4 p = g_hr[tidp];
        p.w = __int_as_float(i);
        g_sorted4[ptOff + (b << nsh) + pos] = p;
    }
}

// ---------------------------------------------------------------------------
// On-the-fly MLP row: relu-free projection value for one HR point, channel
// = lane. Weights/bias in smem (conflict-free); feat via warp-broadcast LDG.
// ---------------------------------------------------------------------------
template <int C>
__device__ __forceinline__ float mlp_row(const float* __restrict__ s_w,
                                         int wOff, int lane,
                                         float hx, float hy, float hz,
                                         const float* __restrict__ fr) {
    float acc = s_w[wOff + (3 + C) * 32 + lane];          // bias
    acc = fmaf(hx, s_w[wOff + lane], acc);
    acc = fmaf(hy, s_w[wOff + 32 + lane], acc);
    acc = fmaf(hz, s_w[wOff + 64 + lane], acc);
    #pragma unroll
    for (int c = 0; c < C; c += 4) {
        float4 f4 = __ldg((const float4*)(fr + c));       // broadcast: 1 sector
        acc = fmaf(f4.x, s_w[wOff + (3 + c) * 32 + lane], acc);
        acc = fmaf(f4.y, s_w[wOff + (4 + c) * 32 + lane], acc);
        acc = fmaf(f4.z, s_w[wOff + (5 + c) * 32 + lane], acc);
        acc = fmaf(f4.w, s_w[wOff + (6 + c) * 32 + lane], acc);
    }
    return acc;
}

// Full warp query for one (set, query): hashed ball query, on-the-fly MLP
// on each hit, max-pool. Max over ALL in-ball hits (hits > nsample prob
// ~1e-17 on this data; pad duplicates never change a max; zero hits -> row 0).
template <int C>
__device__ __forceinline__ float warp_query(const float* __restrict__ s_w,
                                            int wOff, int lane, float4 L,
                                            int base, int segBase,
                                            const float* __restrict__ featB) {
    int cx0 = max(0, (int)floorf(L.x - 1.0f)),   cx1 = min(GX - 1, (int)floorf(L.x + 1.0f));
    int cy0 = max(0, (int)floorf(L.y + 39.0f)),  cy1 = min(GY - 1, (int)floorf(L.y + 41.0f));
    int cz0 = max(0, (int)floorf(L.z + 2.0f)),   cz1 = min(GZ - 1, (int)floorf(L.z + 4.0f));

    // lane r < 9 owns row (cz0 + r/3, cy0 + r%3); fetch its [st, en) range
    int stv = 0, cnt = 0;
    if (lane < 9) {
        int cz = cz0 + lane / 3, cy = cy0 + lane % 3;
        if (cz <= cz1 && cy <= cy1) {
            int rowc = segBase + (cz * GY + cy) * GX;
            stv = __ldg(&g_startArr[rowc + cx0]);
            cnt = __ldg(&g_startArr[rowc + cx1 + 1]) - stv;
        }
    }
    // inclusive warp scan of cnt -> flat candidate space
    int cumi = cnt;
    #pragma unroll
    for (int d = 1; d < 32; d <<= 1) {
        int v = __shfl_up_sync(FULLM, cumi, d);
        if (lane >= d) cumi += v;
    }
    const int T = __shfl_sync(FULLM, cumi, 31);

    float maxv = -CUDART_INF_F;
    int hits = 0;
    for (int b0 = 0; b0 < T; b0 += 32) {
        int g = b0 + lane;
        int rsel = 0, cihit = 0; bool found = false;
        #pragma unroll
        for (int r = 0; r < 9; ++r) {
            int ci = __shfl_sync(FULLM, cumi, r);
            if (!found && g < ci) { found = true; rsel = r; cihit = ci; }
        }
        int str = __shfl_sync(FULLM, stv, rsel);
        int cnr = __shfl_sync(FULLM, cnt, rsel);
        float4 p = make_float4(0.f, 0.f, 0.f, 0.f);
        bool hit = false;
        if (found) {
            int j = str + g - (cihit - cnr);
            p = __ldg(&g_sorted4[base + j]);
            // exact fp32, no contraction: (dx^2+dy^2)+dz^2 < 1
            float dx = __fadd_rn(L.x, -p.x);
            float dy = __fadd_rn(L.y, -p.y);
            float dz = __fadd_rn(L.z, -p.z);
            float d2 = __fadd_rn(__fadd_rn(__fmul_rn(dx, dx), __fmul_rn(dy, dy)),
                                 __fmul_rn(dz, dz));
            hit = d2 < 1.0f;
        }
        unsigned m = __ballot_sync(FULLM, hit);
        hits += __popc(m);
        while (m) {
            int r = __ffs(m) - 1;
            m &= m - 1;
            float hx = __shfl_sync(FULLM, p.x, r);
            float hy = __shfl_sync(FULLM, p.y, r);
            float hz = __shfl_sync(FULLM, p.z, r);
            int   ih = __shfl_sync(FULLM, __float_as_int(p.w), r);
            float v = mlp_row<C>(s_w, wOff, lane, hx, hy, hz,
                                 featB + (size_t)ih * C);
            maxv = fmaxf(maxv, v);
        }
    }
    if (hits == 0) {                              // no neighbor -> index 0
        float4 p0 = __ldg(&g_hr[base]);
        maxv = mlp_row<C>(s_w, wOff, lane, p0.x, p0.y, p0.z, featB);
    }
    return maxv;
}

// ---------------------------------------------------------------------------
// K3: fused query (on-the-fly MLP + max-pool) + final GEMM/BN/ReLU.
// Block = 12 warps = 3 sets x 4 queries; then 256 threads do 4 rows x 64 out.
// ---------------------------------------------------------------------------
__global__ __launch_bounds__(384) void query_out_kernel(
        const float* __restrict__ lrf,
        const float* __restrict__ f1, const float* __restrict__ f2,
        const float* __restrict__ f3,
        const float* __restrict__ w14, const float* __restrict__ b14,
        const float* __restrict__ w24, const float* __restrict__ b24,
        const float* __restrict__ w34, const float* __restrict__ b34,
        const float* __restrict__ wout,
        const float* __restrict__ gamma, const float* __restrict__ beta,
        const float* __restrict__ mean,  const float* __restrict__ var,
        float* __restrict__ out) {
    __shared__ float s_w[WTOT];
    __shared__ float s_grp[4][96];
    const int tid  = threadIdx.x;

    // stage all grouper weights+biases into smem
    for (int i = tid; i < 608;  i += 384) s_w[WOFF1 + i] = __ldg(w14 + i);
    for (int i = tid; i < 1120; i += 384) s_w[WOFF2 + i] = __ldg(w24 + i);
    for (int i = tid; i < 2144; i += 384) s_w[WOFF3 + i] = __ldg(w34 + i);
    if (tid < 32) {
        s_w[WOFF1 + 608 + tid]  = __ldg(b14 + tid);
        s_w[WOFF2 + 1120 + tid] = __ldg(b24 + tid);
        s_w[WOFF3 + 2144 + tid] = __ldg(b34 + tid);
    }
    __syncthreads();

    const int wq   = tid >> 5, lane = tid & 31;
    const int qloc = wq & 3,   s    = wq >> 2;          // set 0..2
    const int q    = blockIdx.x * 4 + qloc;
    const int b    = q >> 12;                            // M_PTS = 4096
    const float4 L = g_lr[q];

    float maxv, qp;
    if (s == 0) {
        maxv = warp_query<16>(s_w, WOFF1, lane, L, PT1 + b * N1,
                              (0 * 2 + b) * SEGSTRIDE, f1 + (size_t)b * N1 * 16);
        qp = fmaf(L.x, s_w[WOFF1 + lane],
             fmaf(L.y, s_w[WOFF1 + 32 + lane],
                  __fmul_rn(L.z, s_w[WOFF1 + 64 + lane])));
    } else if (s == 1) {
        maxv = warp_query<32>(s_w, WOFF2, lane, L, PT2 + b * N2,
                              (1 * 2 + b) * SEGSTRIDE, f2 + (size_t)b * N2 * 32);
        qp = fmaf(L.x, s_w[WOFF2 + lane],
             fmaf(L.y, s_w[WOFF2 + 32 + lane],
                  __fmul_rn(L.z, s_w[WOFF2 + 64 + lane])));
    } else {
        maxv = warp_query<64>(s_w, WOFF3, lane, L, PT3 + b * N3,
                              (2 * 2 + b) * SEGSTRIDE, f3 + (size_t)b * N3 * 64);
        qp = fmaf(L.x, s_w[WOFF3 + lane],
             fmaf(L.y, s_w[WOFF3 + 32 + lane],
                  __fmul_rn(L.z, s_w[WOFF3 + 64 + lane])));
    }
    s_grp[qloc][32 * s + lane] = fmaxf(maxv - qp, 0.0f);
    __syncthreads();

    // ---- fused out: relu(BN(cat[lrf, grp] @ wout)) for 4 rows x 64 channels
    if (tid < 256) {
        const int ry = tid >> 6, o = tid & 63;
        const int r  = blockIdx.x * 4 + ry;
        const float* lr = lrf + (size_t)r * 64;
        float a0 = 0.f, a1 = 0.f, a2 = 0.f, a3 = 0.f;
        #pragma unroll 4
        for (int c = 0; c < 64; c += 4) {
            a0 = fmaf(__ldg(lr + c),     __ldg(wout + (c)     * 64 + o), a0);
            a1 = fmaf(__ldg(lr + c + 1), __ldg(wout + (c + 1) * 64 + o), a1);
            a2 = fmaf(__ldg(lr + c + 2), __ldg(wout + (c + 2) * 64 + o), a2);
            a3 = fmaf(__ldg(lr + c + 3), __ldg(wout + (c + 3) * 64 + o), a3);
        }
        #pragma unroll 4
        for (int c = 0; c < 96; c += 4) {
            a0 = fmaf(s_grp[ry][c],     __ldg(wout + (64 + c)     * 64 + o), a0);
            a1 = fmaf(s_grp[ry][c + 1], __ldg(wout + (64 + c + 1) * 64 + o), a1);
            a2 = fmaf(s_grp[ry][c + 2], __ldg(wout + (64 + c + 2) * 64 + o), a2);
            a3 = fmaf(s_grp[ry][c + 3], __ldg(wout + (64 + c + 3) * 64 + o), a3);
        }
        float acc = (a0 + a1) + (a2 + a3);
        float sc = __ldg(gamma + o) * rsqrtf(__ldg(var + o) + 1e-3f);
        float y  = fmaf(acc - __ldg(mean + o), sc, __ldg(beta + o));
        out[(size_t)r * 64 + o] = fmaxf(y, 0.0f);
    }
}

// ---------------------------------------------------------------------------
extern "C" void kernel_launch(void* const* d_in, const int* in_sizes, int n_in,
                              void* d_out, int out_size) {
    const int*   lr_idx  = (const int*)  d_in[0];
    const int*   hr1_idx = (const int*)  d_in[1];
    const int*   hr2_idx = (const int*)  d_in[2];
    const int*   hr3_idx = (const int*)  d_in[3];
    const float* lr_feat = (const float*)d_in[4];
    const float* h1_feat = (const float*)d_in[5];
    const float* h2_feat = (const float*)d_in[6];
    const float* h3_feat = (const float*)d_in[7];
    const float* w14 = (const float*)d_in[8];
    const float* b14 = (const float*)d_in[9];
    const float* w24 = (const float*)d_in[10];
    const float* b24 = (const float*)d_in[11];
    const float* w34 = (const float*)d_in[12];
    const float* b34 = (const float*)d_in[13];
    const float* w_out    = (const float*)d_in[14];
    const float* bn_gamma = (const float*)d_in[15];
    const float* bn_beta  = (const float*)d_in[16];
    const float* bn_mean  = (const float*)d_in[17];
    const float* bn_var   = (const float*)d_in[18];
    float* out = (float*)d_out;

    prep_kernel<<<(NQ + NPT) / 256, 256>>>(lr_idx, hr1_idx, hr2_idx, hr3_idx);
    scan_scatter_kernel<<<NSEG, 1024>>>();
    query_out_kernel<<<NQ / 4, 384>>>(lr_feat, h1_feat, h2_feat, h3_feat,
                                      w14, b14, w24, b24, w34, b34, w_out,
                                      bn_gamma, bn_beta, bn_mean, bn_var, out);
}

// round 8
// speedup vs baseline: 1.5357x; 1.5357x over previous
#include <cuda_runtime.h>
#include <math_constants.h>

// ---------------------------------------------------------------------------
// Problem constants
// ---------------------------------------------------------------------------
#define BATCH 2
#define M_PTS 4096
#define NQ (BATCH * M_PTS)          // 8192 queries
#define N1 16384
#define N2 8192
#define N3 4096
#define PT1 0                        // set-major point offsets (batch folded in)
#define PT2 32768
#define PT3 49152
#define NPT 57344                    // total HR points (all sets, both batches)

// spatial hash grid: 1m cells covering x[0,72) y[-40,40) z[-3,1)
#define GX 72
#define GY 80
#define GZ 4
#define NCELL (GX * GY * GZ)         // 23040
#define SEGSTRIDE (NCELL + 1)        // +1 sentinel for range-end lookups
#define NSEG 6                       // 3 sets x 2 batches
#define TOTC (NSEG * SEGSTRIDE)

#define FULLM 0xffffffffu
typedef unsigned long long ull;

// ---------------------------------------------------------------------------
// Static device scratch (no allocations allowed).
// g_cnt: prep increments, scatter decrements back to zero -> self-restoring
// across graph replays (no memset needed).
// ---------------------------------------------------------------------------
__device__ float4 g_lr[NQ];
__device__ float4 g_hr[NPT];
__device__ float  g_proj[NPT * 32];
__device__ int    g_cellid[NPT];
__device__ int    g_cnt[TOTC];
__device__ int    g_startArr[TOTC];   // per-segment exclusive prefix + sentinel
__device__ float4 g_sorted4[NPT];     // (x,y,z, idx-as-float), cell-grouped

// ---------------------------------------------------------------------------
// f32x2 packed-FMA helpers (sm_103a)
// ---------------------------------------------------------------------------
__device__ __forceinline__ ull pack2(float a, float b) {
    ull r; asm("mov.b64 %0, {%1, %2};" : "=l"(r) : "f"(a), "f"(b)); return r;
}
__device__ __forceinline__ void fma2(ull& d, ull a, ull b) {
    asm("fma.rn.f32x2 %0, %1, %2, %0;" : "+l"(d) : "l"(a), "l"(b));
}
__device__ __forceinline__ float2 unpack2(ull v) {
    float2 f; asm("mov.b64 {%0, %1}, %2;" : "=f"(f.x), "=f"(f.y) : "l"(v)); return f;
}

// ---------------------------------------------------------------------------
// prep body: xyz (exact ref rounding) + cell id + cell histogram
// ---------------------------------------------------------------------------
__device__ __forceinline__ void prep_body(int blk,
                                          const int* __restrict__ lr_idx,
                                          const int* __restrict__ h1_idx,
                                          const int* __restrict__ h2_idx,
                                          const int* __restrict__ h3_idx) {
    int tid = blk * 256 + threadIdx.x;  // 65536 = NQ + NPT
    const int* idx; int s, local, nsh = 0, ptOff = 0;
    float vx, vy, vz;
    if (tid < NQ) {
        s = -1; local = tid; idx = lr_idx; vx = 0.4f; vy = 0.4f; vz = 1.0f;
    } else {
        int p = tid - NQ;
        if (p < PT2)      { s = 0; local = p;       nsh = 14; ptOff = PT1; idx = h1_idx; vx = 0.05f; vy = 0.05f; vz = 0.1f; }
        else if (p < PT3) { s = 1; local = p - PT2; nsh = 13; ptOff = PT2; idx = h2_idx; vx = 0.1f;  vy = 0.1f;  vz = 0.2f; }
        else              { s = 2; local = p - PT3; nsh = 12; ptOff = PT3; idx = h3_idx; vx = 0.2f;  vy = 0.2f;  vz = 0.4f; }
    }
    int zi = idx[3 * local], yi = idx[3 * local + 1], xi = idx[3 * local + 2];
    // exact replication of ((i*vs)+off)+0.5*vs, no fma contraction
    float fx = __fadd_rn(__fadd_rn(__fmul_rn((float)xi, vx), 0.0f),   __fmul_rn(0.5f, vx));
    float fy = __fadd_rn(__fadd_rn(__fmul_rn((float)yi, vy), -40.0f), __fmul_rn(0.5f, vy));
    float fz = __fadd_rn(__fadd_rn(__fmul_rn((float)zi, vz), -3.0f),  __fmul_rn(0.5f, vz));
    float4 p4 = make_float4(fx, fy, fz, 0.0f);
    if (s < 0) {
        g_lr[local] = p4;
    } else {
        int gp = ptOff + local;
        g_hr[gp] = p4;
        int b = local >> nsh;
        int cx = (int)floorf(fx);
        int cy = (int)floorf(fy + 40.0f);
        int cz = (int)floorf(fz + 3.0f);
        int gc = (s * 2 + b) * SEGSTRIDE + (cz * GY + cy) * GX + cx;
        g_cellid[gp] = gc;
        atomicAdd(&g_cnt[gc], 1);
    }
}

// ---------------------------------------------------------------------------
// proj body: per-HR-point projection with f32x2 FMA. Computes its own xyz
// (independent of prep). thread = (point, 8 channels); 64-pt tiles.
// ---------------------------------------------------------------------------
template <int C>
__device__ __forceinline__ void proj_body(float* s_ws, int blk,
        const int* __restrict__ idx, const float* __restrict__ feat,
        const float* __restrict__ w, const float* __restrict__ bias,
        int ptBase, float vx, float vy, float vz) {
    const int tid = threadIdx.x;
    const int p   = tid >> 2;                    // 0..63 point within tile
    const int co  = (tid & 3) * 8;               // channel group offset
    const int nW  = (3 + C) * 32;
    for (int i = tid; i < nW; i += 256) s_ws[i] = __ldg(w + i);
    if (tid < 32) s_ws[nW + tid] = __ldg(bias + tid);

    const int local = blk * 64 + p;              // in-set point (batch folded)
    int zi = __ldg(idx + 3 * local), yi = __ldg(idx + 3 * local + 1),
        xi = __ldg(idx + 3 * local + 2);
    // exact replication of ((i*vs)+off)+0.5*vs, no fma contraction
    float fx = __fadd_rn(__fadd_rn(__fmul_rn((float)xi, vx), 0.0f),   __fmul_rn(0.5f, vx));
    float fy = __fadd_rn(__fadd_rn(__fmul_rn((float)yi, vy), -40.0f), __fmul_rn(0.5f, vy));
    float fz = __fadd_rn(__fadd_rn(__fmul_rn((float)zi, vz), -3.0f),  __fmul_rn(0.5f, vz));
    __syncthreads();

    ull acc2[4];
    {
        const ull* b2 = (const ull*)&s_ws[nW + co];
        acc2[0] = b2[0]; acc2[1] = b2[1]; acc2[2] = b2[2]; acc2[3] = b2[3];
    }
    const float v3[3] = {fx, fy, fz};
    #pragma unroll
    for (int r = 0; r < 3; ++r) {
        ull vp = pack2(v3[r], v3[r]);
        ulonglong2 wa = *(const ulonglong2*)&s_ws[r * 32 + co];
        ulonglong2 wb = *(const ulonglong2*)&s_ws[r * 32 + co + 4];
        fma2(acc2[0], vp, wa.x); fma2(acc2[1], vp, wa.y);
        fma2(acc2[2], vp, wb.x); fma2(acc2[3], vp, wb.y);
    }
    const float* f = feat + (size_t)local * C;
    #pragma unroll
    for (int c = 0; c < C; c += 4) {
        float4 f4 = __ldg((const float4*)(f + c));
        float fv[4] = {f4.x, f4.y, f4.z, f4.w};
        #pragma unroll
        for (int k = 0; k < 4; ++k) {
            ull fp = pack2(fv[k], fv[k]);
            ulonglong2 wa = *(const ulonglong2*)&s_ws[(3 + c + k) * 32 + co];
            ulonglong2 wb = *(const ulonglong2*)&s_ws[(3 + c + k) * 32 + co + 4];
            fma2(acc2[0], fp, wa.x); fma2(acc2[1], fp, wa.y);
            fma2(acc2[2], fp, wb.x); fma2(acc2[3], fp, wb.y);
        }
    }
    float2 u0 = unpack2(acc2[0]), u1 = unpack2(acc2[1]);
    float2 u2 = unpack2(acc2[2]), u3 = unpack2(acc2[3]);
    float* dst = g_proj + ((size_t)(ptBase + local) << 5) + co;
    *(float4*)dst       = make_float4(u0.x, u0.y, u1.x, u1.y);
    *(float4*)(dst + 4) = make_float4(u2.x, u2.y, u3.x, u3.y);
}

// ---------------------------------------------------------------------------
// K1 (mega): blocks 0..895 = proj (3 sets), 896..1151 = prep.
// proj and prep are independent; co-residency gives the concurrency the
// R6 fork/join achieved, with zero event nodes.
// ---------------------------------------------------------------------------
__global__ __launch_bounds__(256) void mega_kernel(
        const int* __restrict__ lr_idx,  const int* __restrict__ h1_idx,
        const int* __restrict__ h2_idx,  const int* __restrict__ h3_idx,
        const float* __restrict__ f1, const float* __restrict__ f2,
        const float* __restrict__ f3,
        const float* __restrict__ w14, const float* __restrict__ b14,
        const float* __restrict__ w24, const float* __restrict__ b24,
        const float* __restrict__ w34, const float* __restrict__ b34) {
    __shared__ float s_ws[2176];
    int bx = blockIdx.x;
    if (bx < 128)       proj_body<64>(s_ws, bx,       h3_idx, f3, w34, b34, PT3, 0.2f,  0.2f,  0.4f);
    else if (bx < 384)  proj_body<32>(s_ws, bx - 128, h2_idx, f2, w24, b24, PT2, 0.1f,  0.1f,  0.2f);
    else if (bx < 896)  proj_body<16>(s_ws, bx - 384, h1_idx, f1, w14, b14, PT1, 0.05f, 0.05f, 0.1f);
    else                prep_body(bx - 896, lr_idx, h1_idx, h2_idx, h3_idx);
}

// ---------------------------------------------------------------------------
// K2: per-segment exclusive prefix sum over cell counts (6 blocks) + sentinel
// ---------------------------------------------------------------------------
#define CHUNK 23   // ceil(23040 / 1024)
__global__ void scan_kernel() {
    __shared__ int warpTot[32];
    int base = blockIdx.x * SEGSTRIDE;
    int t = threadIdx.x, lane = t & 31, wid = t >> 5;
    int c0 = t * CHUNK;
    int sum = 0;
    #pragma unroll
    for (int k = 0; k < CHUNK; ++k) {
        int c = c0 + k;
        if (c < NCELL) sum += g_cnt[base + c];
    }
    int inc = sum;
    #pragma unroll
    for (int d = 1; d < 32; d <<= 1) {
        int u = __shfl_up_sync(FULLM, inc, d);
        if (lane >= d) inc += u;
    }
    if (lane == 31) warpTot[wid] = inc;
    __syncthreads();
    if (wid == 0) {
        int wv = warpTot[lane];
        #pragma unroll
        for (int d = 1; d < 32; d <<= 1) {
            int u = __shfl_up_sync(FULLM, wv, d);
            if (lane >= d) wv += u;
        }
        warpTot[lane] = wv;
    }
    __syncthreads();
    int ex = inc - sum + (wid > 0 ? warpTot[wid - 1] : 0);
    #pragma unroll
    for (int k = 0; k < CHUNK; ++k) {
        int c = c0 + k;
        if (c < NCELL) {
            int cc = g_cnt[base + c];
            g_startArr[base + c] = ex;
            ex += cc;
        }
    }
    if (t == 1023) g_startArr[base + NCELL] = ex;   // sentinel = segment total
}

// ---------------------------------------------------------------------------
// K3: scatter into cell-grouped order; decrements g_cnt back to zero.
// ---------------------------------------------------------------------------
__global__ void scatter_kernel() {
    int tid = blockIdx.x * blockDim.x + threadIdx.x;  // NPT threads
    if (tid >= NPT) return;
    int nsh, ptOff;
    if (tid < PT2)      { nsh = 14; ptOff = PT1; }
    else if (tid < PT3) { nsh = 13; ptOff = PT2; }
    else                { nsh = 12; ptOff = PT3; }
    int local = tid - ptOff;
    int gc = g_cellid[tid];
    int pos = g_startArr[gc] + atomicAdd(&g_cnt[gc], -1) - 1;
    int b = local >> nsh;
    int i = local - (b << nsh);                  // in-batch index
    float4 p = g_hr[tid];
    p.w = __int_as_float(i);
    g_sorted4[ptOff + (b << nsh) + pos] = p;
}

// ---------------------------------------------------------------------------
// K4: fused hashed ball-query + max-pool + final GEMM/BN/ReLU.
// Block = 12 warps = 3 sets x 4 queries; then 256 threads do 4 rows x 64 out.
// Hit drain 4-way unrolled so proj-row gathers overlap.
// Max over ALL in-ball hits (hits > nsample prob ~1e-17 on this data;
// pad duplicates never change a max; zero hits -> proj row of index 0).
// ---------------------------------------------------------------------------
__global__ __launch_bounds__(384) void query_out_kernel(
        const float* __restrict__ lrf,
        const float* __restrict__ w14, const float* __restrict__ w24,
        const float* __restrict__ w34,
        const float* __restrict__ wout,
        const float* __restrict__ gamma, const float* __restrict__ beta,
        const float* __restrict__ mean,  const float* __restrict__ var,
        float* __restrict__ out) {
    __shared__ float s_grp[4][96];
    const int tid  = threadIdx.x;
    const int wq   = tid >> 5, lane = tid & 31;
    const int qloc = wq & 3,   s    = wq >> 2;          // set 0..2
    const int q    = blockIdx.x * 4 + qloc;
    int N, ptOff; const float* w;
    if (s == 0)      { N = N1; ptOff = PT1; w = w14; }
    else if (s == 1) { N = N2; ptOff = PT2; w = w24; }
    else             { N = N3; ptOff = PT3; w = w34; }
    const int b = q >> 12;                               // M_PTS = 4096
    const int base = ptOff + b * N;
    const int segBase = (s * 2 + b) * SEGSTRIDE;

    const float4 L = g_lr[q];
    int cx0 = max(0, (int)floorf(L.x - 1.0f)),   cx1 = min(GX - 1, (int)floorf(L.x + 1.0f));
    int cy0 = max(0, (int)floorf(L.y + 39.0f)),  cy1 = min(GY - 1, (int)floorf(L.y + 41.0f));
    int cz0 = max(0, (int)floorf(L.z + 2.0f)),   cz1 = min(GZ - 1, (int)floorf(L.z + 4.0f));

    // lane r < 9 owns row (cz0 + r/3, cy0 + r%3); fetch its [st, en) range
    int stv = 0, cnt = 0;
    if (lane < 9) {
        int cz = cz0 + lane / 3, cy = cy0 + lane % 3;
        if (cz <= cz1 && cy <= cy1) {
            int rowc = segBase + (cz * GY + cy) * GX;
            stv = __ldg(&g_startArr[rowc + cx0]);
            cnt = __ldg(&g_startArr[rowc + cx1 + 1]) - stv;
        }
    }
    // inclusive warp scan of cnt -> flat candidate space
    int cumi = cnt;
    #pragma unroll
    for (int d = 1; d < 32; d <<= 1) {
        int v = __shfl_up_sync(FULLM, cumi, d);
        if (lane >= d) cumi += v;
    }
    const int T = __shfl_sync(FULLM, cumi, 31);

    float maxv = -CUDART_INF_F;
    int hits = 0;
    for (int b0 = 0; b0 < T; b0 += 32) {
        int g = b0 + lane;
        int rsel = 0, cihit = 0; bool found = false;
        #pragma unroll
        for (int r = 0; r < 9; ++r) {
            int ci = __shfl_sync(FULLM, cumi, r);
            if (!found && g < ci) { found = true; rsel = r; cihit = ci; }
        }
        int str = __shfl_sync(FULLM, stv, rsel);
        int cnr = __shfl_sync(FULLM, cnt, rsel);
        int i = 0; bool hit = false;
        if (found) {
            int j = str + g - (cihit - cnr);
            float4 p = __ldg(&g_sorted4[base + j]);
            // exact fp32, no contraction: (dx^2+dy^2)+dz^2 < 1
            float dx = __fadd_rn(L.x, -p.x);
            float dy = __fadd_rn(L.y, -p.y);
            float dz = __fadd_rn(L.z, -p.z);
            float d2 = __fadd_rn(__fadd_rn(__fmul_rn(dx, dx), __fmul_rn(dy, dy)),
                                 __fmul_rn(dz, dz));
            hit = d2 < 1.0f;
            i = __float_as_int(p.w);
        }
        unsigned m = __ballot_sync(FULLM, hit);
        hits += __popc(m);
        while (m) {                      // 4-way unrolled: gathers overlap
            int r0 = __ffs(m) - 1; m &= m - 1;
            int r1 = -1, r2 = -1, r3 = -1;
            if (m) { r1 = __ffs(m) - 1; m &= m - 1; }
            if (m) { r2 = __ffs(m) - 1; m &= m - 1; }
            if (m) { r3 = __ffs(m) - 1; m &= m - 1; }
            int i0 = __shfl_sync(FULLM, i, r0);
            int i1 = __shfl_sync(FULLM, i, r1 < 0 ? 0 : r1);
            int i2 = __shfl_sync(FULLM, i, r2 < 0 ? 0 : r2);
            int i3 = __shfl_sync(FULLM, i, r3 < 0 ? 0 : r3);
            float v0 = __ldg(&g_proj[((size_t)(base + i0) << 5) + lane]);
            float v1 = r1 >= 0 ? __ldg(&g_proj[((size_t)(base + i1) << 5) + lane]) : -CUDART_INF_F;
            float v2 = r2 >= 0 ? __ldg(&g_proj[((size_t)(base + i2) << 5) + lane]) : -CUDART_INF_F;
            float v3 = r3 >= 0 ? __ldg(&g_proj[((size_t)(base + i3) << 5) + lane]) : -CUDART_INF_F;
            maxv = fmaxf(maxv, fmaxf(fmaxf(v0, v1), fmaxf(v2, v3)));
        }
    }
    if (hits == 0)
        maxv = __ldg(&g_proj[((size_t)base << 5) + lane]);
    float qp = fmaf(L.x, __ldg(w + lane),
               fmaf(L.y, __ldg(w + 32 + lane),
                    __fmul_rn(L.z, __ldg(w + 64 + lane))));
    s_grp[qloc][32 * s + lane] = fmaxf(maxv - qp, 0.0f);
    __syncthreads();

    // ---- fused out: relu(BN(cat[lrf, grp] @ wout)) for 4 rows x 64 channels
    if (tid < 256) {
        const int ry = tid >> 6, o = tid & 63;
        const int r  = blockIdx.x * 4 + ry;
        const float* lr = lrf + (size_t)r * 64;
        float a0 = 0.f, a1 = 0.f, a2 = 0.f, a3 = 0.f;
        #pragma unroll 4
        for (int c = 0; c < 64; c += 4) {
            a0 = fmaf(__ldg(lr + c),     __ldg(wout + (c)     * 64 + o), a0);
            a1 = fmaf(__ldg(lr + c + 1), __ldg(wout + (c + 1) * 64 + o), a1);
            a2 = fmaf(__ldg(lr + c + 2), __ldg(wout + (c + 2) * 64 + o), a2);
            a3 = fmaf(__ldg(lr + c + 3), __ldg(wout + (c + 3) * 64 + o), a3);
        }
        #pragma unroll 4
        for (int c = 0; c < 96; c += 4) {
            a0 = fmaf(s_grp[ry][c],     __ldg(wout + (64 + c)     * 64 + o), a0);
            a1 = fmaf(s_grp[ry][c + 1], __ldg(wout + (64 + c + 1) * 64 + o), a1);
            a2 = fmaf(s_grp[ry][c + 2], __ldg(wout + (64 + c + 2) * 64 + o), a2);
            a3 = fmaf(s_grp[ry][c + 3], __ldg(wout + (64 + c + 3) * 64 + o), a3);
        }
        float acc = (a0 + a1) + (a2 + a3);
        float sc = __ldg(gamma + o) * rsqrtf(__ldg(var + o) + 1e-3f);
        float y  = fmaf(acc - __ldg(mean + o), sc, __ldg(beta + o));
        out[(size_t)r * 64 + o] = fmaxf(y, 0.0f);
    }
}

// ---------------------------------------------------------------------------
extern "C" void kernel_launch(void* const* d_in, const int* in_sizes, int n_in,
                              void* d_out, int out_size) {
    const int*   lr_idx  = (const int*)  d_in[0];
    const int*   hr1_idx = (const int*)  d_in[1];
    const int*   hr2_idx = (const int*)  d_in[2];
    const int*   hr3_idx = (const int*)  d_in[3];
    const float* lr_feat = (const float*)d_in[4];
    const float* h1_feat = (const float*)d_in[5];
    const float* h2_feat = (const float*)d_in[6];
    const float* h3_feat = (const float*)d_in[7];
    const float* w14 = (const float*)d_in[8];
    const float* b14 = (const float*)d_in[9];
    const float* w24 = (const float*)d_in[10];
    const float* b24 = (const float*)d_in[11];
    const float* w34 = (const float*)d_in[12];
    const float* b34 = (const float*)d_in[13];
    const float* w_out    = (const float*)d_in[14];
    const float* bn_gamma = (const float*)d_in[15];
    const float* bn_beta  = (const float*)d_in[16];
    const float* bn_mean  = (const float*)d_in[17];
    const float* bn_var   = (const float*)d_in[18];
    float* out = (float*)d_out;

    mega_kernel<<<1152, 256>>>(lr_idx, hr1_idx, hr2_idx, hr3_idx,
                               h1_feat, h2_feat, h3_feat,
                               w14, b14, w24, b24, w34, b34);
    scan_kernel<<<NSEG, 1024>>>();
    scatter_kernel<<<NPT / 256, 256>>>();
    query_out_kernel<<<NQ / 4, 384>>>(lr_feat, w14, w24, w34, w_out,
                                      bn_gamma, bn_beta, bn_mean, bn_var, out);
}